// round 3
// baseline (speedup 1.0000x reference)
#include <cuda_runtime.h>

#define D_DIM 256
#define NCLS 100
#define K1_CTAS 64
#define K1_THREADS 256
#define GSIZE (NCLS * D_DIM)   // 25600 floats = 100 KB

// Scratch: __device__ globals (allocation forbidden). All partials fully
// overwritten each launch; g_counter reset by finishing CTA -> graph-replay
// deterministic.
__device__ float g_part[(size_t)K1_CTAS * GSIZE];  // per-CTA per-class sums
__device__ float s_part[(size_t)K1_CTAS * D_DIM];  // per-CTA total-sum vector
__device__ float t_part[K1_CTAS];                  // per-CTA sum of squares
__device__ double sumsq_cls[NCLS];                 // ||g_c||^2 per class (fp64)
__device__ unsigned int g_counter = 0;             // last-CTA ticket

// ---------------------------------------------------------------------------
// K1: stream feat. Thread tid owns column tid (coalesced LDG.32). Per-CTA
// smem privatization of the 100x256 class-sum matrix (thread t only touches
// column t -> conflict-free). Label dtype (int64 vs int32) sniffed
// deterministically from data: int32 labels in [0,100) make the "high words"
// of a fake-int64 read nonzero with overwhelming probability.
// ---------------------------------------------------------------------------
__global__ void k_accum(const float* __restrict__ feat,
                        const void* __restrict__ label_raw, int B) {
    extern __shared__ float sG[];   // [NCLS * D_DIM]
    const int tid = threadIdx.x;
    const int cta = blockIdx.x;

    #pragma unroll 4
    for (int i = tid; i < GSIZE; i += K1_THREADS) sG[i] = 0.0f;

    // --- label dtype sniff (thread 0, deterministic) ---
    __shared__ int s_is64;
    if (tid == 0) {
        const unsigned long long* p = (const unsigned long long*)label_raw;
        int n = (B < 16) ? B : 16;
        int ok = 1;
        for (int i = 0; i < n; ++i)
            if (p[i] >= 100ULL) { ok = 0; break; }   // high word set or junk
        s_is64 = ok;
    }
    __syncthreads();
    const int is64 = s_is64;

    const int rows = (B + K1_CTAS - 1) / K1_CTAS;
    const int r0 = cta * rows;
    const int r1 = (r0 + rows < B) ? (r0 + rows) : B;

    float t = 0.0f;   // sum v^2 (this column)
    float s = 0.0f;   // sum v   (this column)

    if (is64) {
        const long long* lab = (const long long*)label_raw;
        int r = r0;
        for (; r + 4 <= r1; r += 4) {
            float v0 = feat[(size_t)(r + 0) * D_DIM + tid];
            float v1 = feat[(size_t)(r + 1) * D_DIM + tid];
            float v2 = feat[(size_t)(r + 2) * D_DIM + tid];
            float v3 = feat[(size_t)(r + 3) * D_DIM + tid];
            int l0 = (int)lab[r + 0], l1 = (int)lab[r + 1];
            int l2 = (int)lab[r + 2], l3 = (int)lab[r + 3];
            t = fmaf(v0, v0, t);  s += v0;  sG[l0 * D_DIM + tid] += v0;
            t = fmaf(v1, v1, t);  s += v1;  sG[l1 * D_DIM + tid] += v1;
            t = fmaf(v2, v2, t);  s += v2;  sG[l2 * D_DIM + tid] += v2;
            t = fmaf(v3, v3, t);  s += v3;  sG[l3 * D_DIM + tid] += v3;
        }
        for (; r < r1; ++r) {
            float v = feat[(size_t)r * D_DIM + tid];
            int l = (int)lab[r];
            t = fmaf(v, v, t);  s += v;  sG[l * D_DIM + tid] += v;
        }
    } else {
        const int* lab = (const int*)label_raw;
        int r = r0;
        for (; r + 4 <= r1; r += 4) {
            float v0 = feat[(size_t)(r + 0) * D_DIM + tid];
            float v1 = feat[(size_t)(r + 1) * D_DIM + tid];
            float v2 = feat[(size_t)(r + 2) * D_DIM + tid];
            float v3 = feat[(size_t)(r + 3) * D_DIM + tid];
            int l0 = lab[r + 0], l1 = lab[r + 1];
            int l2 = lab[r + 2], l3 = lab[r + 3];
            t = fmaf(v0, v0, t);  s += v0;  sG[l0 * D_DIM + tid] += v0;
            t = fmaf(v1, v1, t);  s += v1;  sG[l1 * D_DIM + tid] += v1;
            t = fmaf(v2, v2, t);  s += v2;  sG[l2 * D_DIM + tid] += v2;
            t = fmaf(v3, v3, t);  s += v3;  sG[l3 * D_DIM + tid] += v3;
        }
        for (; r < r1; ++r) {
            float v = feat[(size_t)r * D_DIM + tid];
            int l = lab[r];
            t = fmaf(v, v, t);  s += v;  sG[l * D_DIM + tid] += v;
        }
    }
    __syncthreads();

    // per-CTA partials (plain stores, fully overwrite)
    float* gp = g_part + (size_t)cta * GSIZE;
    #pragma unroll 4
    for (int i = tid; i < GSIZE; i += K1_THREADS) gp[i] = sG[i];
    s_part[(size_t)cta * D_DIM + tid] = s;

    // block-reduce t (fixed order -> deterministic)
    __shared__ float red[32];
    #pragma unroll
    for (int o = 16; o > 0; o >>= 1) t += __shfl_down_sync(0xFFFFFFFFu, t, o);
    if ((tid & 31) == 0) red[tid >> 5] = t;
    __syncthreads();
    if (tid == 0) {
        float v = 0.0f;
        #pragma unroll
        for (int w = 0; w < K1_THREADS / 32; ++w) v += red[w];
        t_part[cta] = v;
    }
}

// ---------------------------------------------------------------------------
// K2 (+ fused final): CTA c reduces 64 partials of class c -> ||g_c||^2 (fp64).
// Last CTA (atomic ticket) computes
//   loss = 0.5*||s||^2 - 1.5*sum_c ||g_c||^2 + sum_i ||f_i||^2   (fp64)
// and resets the ticket for the next graph replay.
// ---------------------------------------------------------------------------
__global__ void k_reduce_final(float* __restrict__ out) {
    const int c = blockIdx.x;    // class id, grid = NCLS
    const int d = threadIdx.x;   // 256 threads = D columns

    float g = 0.0f;
    #pragma unroll 8
    for (int p = 0; p < K1_CTAS; ++p)
        g += g_part[(size_t)p * GSIZE + c * D_DIM + d];

    double sq = (double)g * (double)g;
    __shared__ double redd[32];
    #pragma unroll
    for (int o = 16; o > 0; o >>= 1) sq += __shfl_down_sync(0xFFFFFFFFu, sq, o);
    if ((d & 31) == 0) redd[d >> 5] = sq;
    __syncthreads();
    if (d == 0) {
        double v = 0.0;
        #pragma unroll
        for (int w = 0; w < 8; ++w) v += redd[w];
        sumsq_cls[c] = v;
    }

    // last-CTA-done ticket (release via fence before atomic; acquire after)
    __shared__ int s_last;
    if (d == 0) {
        __threadfence();
        unsigned int old = atomicAdd(&g_counter, 1u);
        s_last = (old == (unsigned int)(gridDim.x - 1)) ? 1 : 0;
    }
    __syncthreads();
    if (!s_last) return;
    __threadfence();

    // ---- final combination (one CTA) ----
    float s = 0.0f;
    #pragma unroll 8
    for (int p = 0; p < K1_CTAS; ++p)
        s += s_part[(size_t)p * D_DIM + d];

    double val = 0.5 * (double)s * (double)s;
    if (d < NCLS)    val -= 1.5 * sumsq_cls[d];
    if (d < K1_CTAS) val += (double)t_part[d];

    __shared__ double redf[32];
    #pragma unroll
    for (int o = 16; o > 0; o >>= 1) val += __shfl_down_sync(0xFFFFFFFFu, val, o);
    if ((d & 31) == 0) redf[d >> 5] = val;
    __syncthreads();
    if (d == 0) {
        double v = 0.0;
        #pragma unroll
        for (int w = 0; w < 8; ++w) v += redf[w];
        out[0] = (float)v;
        g_counter = 0;   // reset for next replay
    }
}

// ---------------------------------------------------------------------------
extern "C" void kernel_launch(void* const* d_in, const int* in_sizes, int n_in,
                              void* d_out, int out_size) {
    const float* feat = (const float*)d_in[0];
    const void* label = d_in[1];
    const int B = in_sizes[1];   // label element count = batch size

    cudaFuncSetAttribute(k_accum, cudaFuncAttributeMaxDynamicSharedMemorySize,
                         GSIZE * (int)sizeof(float));

    k_accum<<<K1_CTAS, K1_THREADS, GSIZE * sizeof(float)>>>(feat, label, B);
    k_reduce_final<<<NCLS, D_DIM>>>((float*)d_out);
}

// round 8
// speedup vs baseline: 1.3266x; 1.3266x over previous
#include <cuda_runtime.h>

#define D_DIM 256
#define NCLS 100
#define K1_CTAS 64
#define K1_THREADS 512
#define GSIZE (NCLS * D_DIM)      // 25600 floats = 100 KB
#define K2_THREADS 1024
#define PGRP 4                    // p-groups in K2
#define PPER (K1_CTAS / PGRP)     // 16 partials per thread

// Scratch (__device__ globals; allocation forbidden). Fully overwritten each
// launch; ticket reset by finishing CTA -> graph-replay deterministic.
__device__ float g_part[(size_t)K1_CTAS * GSIZE];
__device__ float s_part[(size_t)K1_CTAS * D_DIM];
__device__ float t_part[K1_CTAS];
__device__ double sumsq_cls[NCLS];
__device__ unsigned int g_counter = 0;

// ---------------------------------------------------------------------------
// K1: 64 CTAs x 512 threads. Column col = tid&255 (coalesced LDG.32); half
// h = tid>>8 owns a private 100KB smem copy (conflict-free: thread only
// touches its column of its copy). Copies merged at writeout.
// ---------------------------------------------------------------------------
__global__ void k_accum(const float* __restrict__ feat,
                        const void* __restrict__ label_raw, int B) {
    extern __shared__ float sG[];          // [2 * GSIZE]
    __shared__ float sS[K1_THREADS];       // per-thread column sums
    __shared__ float red[K1_THREADS / 32];
    __shared__ int s_is64;

    const int tid = threadIdx.x;
    const int col = tid & 255;
    const int h   = tid >> 8;
    const int cta = blockIdx.x;

    #pragma unroll 4
    for (int i = tid; i < 2 * GSIZE; i += K1_THREADS) sG[i] = 0.0f;

    // label dtype sniff (int64 vs silently-downgraded int32), deterministic:
    // int32 labels in [0,100) make a masquerading buffer fail the <100 test
    // in the first 16 fake-int64 words with overwhelming probability.
    if (tid == 0) {
        const unsigned long long* p = (const unsigned long long*)label_raw;
        int n = (B < 16) ? B : 16;
        int ok = 1;
        for (int i = 0; i < n; ++i)
            if (p[i] >= 100ULL) { ok = 0; break; }
        s_is64 = ok;
    }
    __syncthreads();
    const int is64 = s_is64;

    float* myG = sG + h * GSIZE;

    const int rows = (B + K1_CTAS - 1) / K1_CTAS;
    const int base = cta * rows;
    const int end  = (base + rows < B) ? (base + rows) : B;
    const int hr   = (rows + 1) >> 1;
    const int r0   = base + h * hr;
    int r1 = r0 + hr; if (r1 > end) r1 = end;

    float t = 0.0f, s = 0.0f;

    if (is64) {
        const long long* lab = (const long long*)label_raw;
        int r = r0;
        for (; r + 4 <= r1; r += 4) {
            float v0 = feat[(size_t)(r + 0) * D_DIM + col];
            float v1 = feat[(size_t)(r + 1) * D_DIM + col];
            float v2 = feat[(size_t)(r + 2) * D_DIM + col];
            float v3 = feat[(size_t)(r + 3) * D_DIM + col];
            int l0 = (int)lab[r + 0], l1 = (int)lab[r + 1];
            int l2 = (int)lab[r + 2], l3 = (int)lab[r + 3];
            t = fmaf(v0, v0, t);  s += v0;  myG[l0 * D_DIM + col] += v0;
            t = fmaf(v1, v1, t);  s += v1;  myG[l1 * D_DIM + col] += v1;
            t = fmaf(v2, v2, t);  s += v2;  myG[l2 * D_DIM + col] += v2;
            t = fmaf(v3, v3, t);  s += v3;  myG[l3 * D_DIM + col] += v3;
        }
        for (; r < r1; ++r) {
            float v = feat[(size_t)r * D_DIM + col];
            int l = (int)lab[r];
            t = fmaf(v, v, t);  s += v;  myG[l * D_DIM + col] += v;
        }
    } else {
        const int* lab = (const int*)label_raw;
        int r = r0;
        for (; r + 4 <= r1; r += 4) {
            float v0 = feat[(size_t)(r + 0) * D_DIM + col];
            float v1 = feat[(size_t)(r + 1) * D_DIM + col];
            float v2 = feat[(size_t)(r + 2) * D_DIM + col];
            float v3 = feat[(size_t)(r + 3) * D_DIM + col];
            int l0 = lab[r + 0], l1 = lab[r + 1];
            int l2 = lab[r + 2], l3 = lab[r + 3];
            t = fmaf(v0, v0, t);  s += v0;  myG[l0 * D_DIM + col] += v0;
            t = fmaf(v1, v1, t);  s += v1;  myG[l1 * D_DIM + col] += v1;
            t = fmaf(v2, v2, t);  s += v2;  myG[l2 * D_DIM + col] += v2;
            t = fmaf(v3, v3, t);  s += v3;  myG[l3 * D_DIM + col] += v3;
        }
        for (; r < r1; ++r) {
            float v = feat[(size_t)r * D_DIM + col];
            int l = lab[r];
            t = fmaf(v, v, t);  s += v;  myG[l * D_DIM + col] += v;
        }
    }
    sS[tid] = s;
    __syncthreads();

    // merge the two copies, write per-CTA partial (coalesced STG)
    float* gp = g_part + (size_t)cta * GSIZE;
    #pragma unroll 4
    for (int i = tid; i < GSIZE; i += K1_THREADS)
        gp[i] = sG[i] + sG[GSIZE + i];
    if (h == 0)
        s_part[(size_t)cta * D_DIM + col] = sS[col] + sS[col + 256];

    // block-reduce t (fixed order -> deterministic)
    #pragma unroll
    for (int o = 16; o > 0; o >>= 1) t += __shfl_down_sync(0xFFFFFFFFu, t, o);
    if ((tid & 31) == 0) red[tid >> 5] = t;
    __syncthreads();
    if (tid == 0) {
        float v = 0.0f;
        #pragma unroll
        for (int w = 0; w < K1_THREADS / 32; ++w) v += red[w];
        t_part[cta] = v;
    }
}

// ---------------------------------------------------------------------------
// K2: 100 CTAs x 1024 threads. Thread t: d = t%256, pg = t/256 reduces its
// 16 partials (independent loads -> MLP 16); 4-way smem combine; fp64 square
// reduce -> sumsq_cls[c]. Last CTA (ticket) computes the final fp64 sum.
// ---------------------------------------------------------------------------
__global__ void k_reduce_final(float* __restrict__ out) {
    __shared__ float sgg[PGRP][D_DIM];
    __shared__ double redd[8];

    const int c  = blockIdx.x;
    const int t  = threadIdx.x;
    const int d  = t & 255;
    const int pg = t >> 8;

    {
        const float* bp = g_part + (size_t)pg * PPER * GSIZE + (size_t)c * D_DIM + d;
        float g = 0.0f;
        #pragma unroll
        for (int p = 0; p < PPER; ++p) g += bp[(size_t)p * GSIZE];
        sgg[pg][d] = g;
    }
    __syncthreads();

    if (t < D_DIM) {
        float g = sgg[0][d] + sgg[1][d] + sgg[2][d] + sgg[3][d];
        double sq = (double)g * (double)g;
        #pragma unroll
        for (int o = 16; o > 0; o >>= 1) sq += __shfl_down_sync(0xFFFFFFFFu, sq, o);
        if ((d & 31) == 0) redd[d >> 5] = sq;
    }
    __syncthreads();
    if (t == 0) {
        double v = 0.0;
        #pragma unroll
        for (int w = 0; w < 8; ++w) v += redd[w];
        sumsq_cls[c] = v;
    }

    // last-CTA-done ticket (release fence before, acquire fence after)
    __shared__ int s_last;
    if (t == 0) {
        __threadfence();
        unsigned int old = atomicAdd(&g_counter, 1u);
        s_last = (old == (unsigned int)(gridDim.x - 1)) ? 1 : 0;
    }
    __syncthreads();
    if (!s_last) return;
    __threadfence();

    // ---- final combination (this CTA, 1024 threads) ----
    {
        const float* bp = s_part + (size_t)pg * PPER * D_DIM + d;
        float s = 0.0f;
        #pragma unroll
        for (int p = 0; p < PPER; ++p) s += bp[(size_t)p * D_DIM];
        sgg[pg][d] = s;
    }
    __syncthreads();

    if (t < D_DIM) {
        float s = sgg[0][d] + sgg[1][d] + sgg[2][d] + sgg[3][d];
        double val = 0.5 * (double)s * (double)s;
        if (d < NCLS)    val -= 1.5 * sumsq_cls[d];
        if (d < K1_CTAS) val += (double)t_part[d];
        #pragma unroll
        for (int o = 16; o > 0; o >>= 1) val += __shfl_down_sync(0xFFFFFFFFu, val, o);
        if ((d & 31) == 0) redd[d >> 5] = val;
    }
    __syncthreads();
    if (t == 0) {
        double v = 0.0;
        #pragma unroll
        for (int w = 0; w < 8; ++w) v += redd[w];
        out[0] = (float)v;
        g_counter = 0;   // reset for next graph replay
    }
}

// ---------------------------------------------------------------------------
extern "C" void kernel_launch(void* const* d_in, const int* in_sizes, int n_in,
                              void* d_out, int out_size) {
    const float* feat = (const float*)d_in[0];
    const void* label = d_in[1];
    const int B = in_sizes[1];

    cudaFuncSetAttribute(k_accum, cudaFuncAttributeMaxDynamicSharedMemorySize,
                         2 * GSIZE * (int)sizeof(float));

    k_accum<<<K1_CTAS, K1_THREADS, 2 * GSIZE * sizeof(float)>>>(feat, label, B);
    k_reduce_final<<<NCLS, K2_THREADS>>>((float*)d_out);
}